// round 10
// baseline (speedup 1.0000x reference)
#include <cuda_runtime.h>
#include <cuda_bf16.h>

// Problem constants (from setup_inputs): B=32, T=1024, N=256, tau=20, dt=1.
#define BB 32
#define TT 1024
#define NN 256
#define CC 64            // number of t-chunks
#define TC 16            // t-steps per chunk (TT / CC)
#define NV 64            // N / 4 (float4 lanes)
#define QQ 4             // pass2 n-tiles

// Scan carry / reduction scratch (no cudaMalloc allowed -> __device__ globals)
__device__ float g_Tc[BB * CC * NN];   // chunk totals of sum d_j * e^{-j/tau}
__device__ float g_Bc[BB * CC * NN];   // sum s_t^2 * L_t
__device__ float g_Cc[BB * CC * NN];   // sum (s_t * L_t)^2
__device__ float g_partial[BB * QQ];   // per-(b, n-tile) partial sums

// e^{-0.05} and e^{+0.05} (dt/tau = 0.05)
#define R_DECAY 0.95122942450071400910f
#define R_GROW  1.05127109637602411448f
// e^{0.8} (per-chunk step of s, TC=16)
#define R_CHUNK 2.22554092849246760458f
// geometric sum (e^{1.6}-1)/(e^{0.1}-1): A_c = s0(c)^2 * GEO
#define GEO_SUM 37.58673907f

// ---------------------------------------------------------------------------
// Pass 1: per (b, chunk) compute chunk-local scan reductions, float4 over n.
//   p_t = e^{-t/20},  s_t = e^{(t-1023)/20}/20
//   L = local inclusive prefix of d_j * p_j within the chunk.
// Chunk contribution = S_prev^2 * A_c + 2 S_prev * B_c + C_c, carry T_c = L_end.
// A_c depends only on c -> computed analytically in pass2 (not stored here).
// Loads are batched 4 t-steps deep (8x LDG.128 in flight) to lift MLP.
// ---------------------------------------------------------------------------
__global__ void __launch_bounds__(NV) vr_pass1(const float* __restrict__ x,
                                               const float* __restrict__ y) {
    const int b = blockIdx.x;
    const int c = blockIdx.y;
    const int v = threadIdx.x;            // float4 lane: channels 4v..4v+3

    const long long base = ((long long)b * TT + (long long)c * TC) * NN + 4 * v;
    const float4* __restrict__ xp = (const float4*)(x + base);
    const float4* __restrict__ yp = (const float4*)(y + base);

    const float t0 = (float)(c * TC);
    float p = __expf(-t0 * 0.05f);                    // e^{-t0/20}
    float s = __expf((t0 - 1023.0f) * 0.05f) * 0.05f; // e^{(t0-1023)/20}/20

    float L[4]  = {0.f, 0.f, 0.f, 0.f};
    float Ba[4] = {0.f, 0.f, 0.f, 0.f};
    float Ca[4] = {0.f, 0.f, 0.f, 0.f};

#pragma unroll
    for (int kb = 0; kb < TC; kb += 4) {
        float4 xr[4], yr[4];
#pragma unroll
        for (int j = 0; j < 4; j++) {
            xr[j] = __ldcs(xp + (long long)(kb + j) * (NN / 4));
            yr[j] = __ldcs(yp + (long long)(kb + j) * (NN / 4));
        }
#pragma unroll
        for (int j = 0; j < 4; j++) {
            L[0] = fmaf(xr[j].x - yr[j].x, p, L[0]);
            L[1] = fmaf(xr[j].y - yr[j].y, p, L[1]);
            L[2] = fmaf(xr[j].z - yr[j].z, p, L[2]);
            L[3] = fmaf(xr[j].w - yr[j].w, p, L[3]);
#pragma unroll
            for (int i = 0; i < 4; i++) {
                const float g = s * L[i];
                Ba[i] = fmaf(s, g, Ba[i]);
                Ca[i] = fmaf(g, g, Ca[i]);
            }
            p *= R_DECAY;
            s *= R_GROW;
        }
    }

    const int idx = (b * CC + c) * NN + 4 * v;
    *(float4*)&g_Tc[idx] = make_float4(L[0], L[1], L[2], L[3]);
    *(float4*)&g_Bc[idx] = make_float4(Ba[0], Ba[1], Ba[2], Ba[3]);
    *(float4*)&g_Cc[idx] = make_float4(Ca[0], Ca[1], Ca[2], Ca[3]);
}

// ---------------------------------------------------------------------------
// Pass 2: per (b, n), chain chunk carries in t-order:
//   contribution = S^2 * A_c + 2 S * B_c + C_c;  S += T_c.
// A_c = s0(c)^2 * GEO_SUM with s0(c) = e^{(16c-1023)/20}/20 (geometric recur).
// Grid (BB, QQ) x 64 threads: 256 warps for the 6 MB scratch read.
// ---------------------------------------------------------------------------
__global__ void __launch_bounds__(NV) vr_pass2() {
    const int b = blockIdx.x;
    const int q = blockIdx.y;
    const int n = q * NV + threadIdx.x;

    float s0 = __expf(-1023.0f * 0.05f) * 0.05f;  // s at t=0
    float S = 0.0f;
    float acc = 0.0f;
#pragma unroll 8
    for (int c = 0; c < CC; c++) {
        const int idx = (b * CC + c) * NN + n;
        const float A = (s0 * s0) * GEO_SUM;
        acc += fmaf(S * S, A, fmaf(2.0f * S, g_Bc[idx], g_Cc[idx]));
        S += g_Tc[idx];
        s0 *= R_CHUNK;
    }

    __shared__ float sh[NV];
    sh[threadIdx.x] = acc;
    __syncthreads();
#pragma unroll
    for (int st = NV / 2; st > 0; st >>= 1) {
        if (threadIdx.x < st) sh[threadIdx.x] += sh[threadIdx.x + st];
        __syncthreads();
    }
    if (threadIdx.x == 0) g_partial[b * QQ + q] = sh[0];
}

// ---------------------------------------------------------------------------
// Pass 3: deterministic fixed-order final reduce + mean over batch.
// ---------------------------------------------------------------------------
__global__ void vr_pass3(float* __restrict__ out) {
    if (threadIdx.x == 0) {
        float total = 0.0f;
#pragma unroll
        for (int i = 0; i < BB * QQ; i++) total += g_partial[i];
        out[0] = total * (1.0f / (float)BB);
    }
}

extern "C" void kernel_launch(void* const* d_in, const int* in_sizes, int n_in,
                              void* d_out, int out_size) {
    const float* x = (const float*)d_in[0];  // spike_output  [B,T,N]
    const float* y = (const float*)d_in[1];  // target_spikes [B,T,N]
    float* out = (float*)d_out;

    vr_pass1<<<dim3(BB, CC), NV>>>(x, y);
    vr_pass2<<<dim3(BB, QQ), NV>>>();
    vr_pass3<<<1, 32>>>(out);
}

// round 14
// speedup vs baseline: 1.2745x; 1.2745x over previous
#include <cuda_runtime.h>
#include <cuda_bf16.h>

// Problem constants (from setup_inputs): B=32, T=1024, N=256, tau=20, dt=1.
#define BB 32
#define TT 1024
#define NN 256
#define CC 64            // number of t-chunks
#define TC 16            // t-steps per chunk (TT / CC)
#define NV 64            // N / 4 (float4 lanes)
#define QQ 4             // pass2 n-tiles
#define SUBS 4           // pass2 c-splits per channel
#define CPS 16           // chunks per sub (CC / SUBS)

// Scan carry / reduction scratch (no cudaMalloc allowed -> __device__ globals)
__device__ float g_Tc[BB * CC * NN];   // chunk totals of sum d_j * e^{-j/tau}
__device__ float g_Bc[BB * CC * NN];   // sum s_t^2 * L_t
__device__ float g_Cc[BB * CC * NN];   // sum (s_t * L_t)^2
__device__ float g_partial[BB * QQ];   // per-(b, n-tile) partial sums
__device__ unsigned g_done;            // pass2 arrival counter (self-resetting)

// e^{-0.05} and e^{+0.05} (dt/tau = 0.05)
#define R_DECAY 0.95122942450071400910f
#define R_GROW  1.05127109637602411448f
// e^{-0.4}, e^{+0.4}: 8-step jumps for the dual-stream split
#define E_N04   0.67032004603563930074f
#define E_P04   1.49182469764127031782f
// geometric sums of e^{0.1 j}: j<8 and j<16
#define GEO8    11.65284994f
#define GEO16   37.58673907f
// e^{0.8}: per-chunk step of s0 (TC=16)
#define R_CHUNK 2.22554092849246760458f

// ---------------------------------------------------------------------------
// Pass 1: per (b, chunk): float4 over n, chunk split into TWO independent
// 8-step streams (A: t 0..7, B: t 8..15) to double ILP/MLP; exact merge:
//   T  = LA + LB
//   Bc = BA + LA*alphaB + BB          (alphaB = sum of s^2 over stream B)
//   Cc = CA + LA^2*alphaB + 2*LA*BB + CB
// ---------------------------------------------------------------------------
__global__ void __launch_bounds__(NV) vr_pass1(const float* __restrict__ x,
                                               const float* __restrict__ y) {
    const int b = blockIdx.x;
    const int c = blockIdx.y;
    const int v = threadIdx.x;            // float4 lane: channels 4v..4v+3

    const long long base = ((long long)b * TT + (long long)c * TC) * NN + 4 * v;
    const float4* __restrict__ xp = (const float4*)(x + base);
    const float4* __restrict__ yp = (const float4*)(y + base);

    const float t0 = (float)(c * TC);
    float pA = __expf(-t0 * 0.05f);                    // e^{-t0/20}
    float sA = __expf((t0 - 1023.0f) * 0.05f) * 0.05f; // e^{(t0-1023)/20}/20
    float pB = pA * E_N04;
    float sB = sA * E_P04;
    const float alphaB = (sB * sB) * GEO8;             // sum s^2 over stream B

    float LA[4] = {0.f,0.f,0.f,0.f}, BA[4] = {0.f,0.f,0.f,0.f}, CA[4] = {0.f,0.f,0.f,0.f};
    float LB[4] = {0.f,0.f,0.f,0.f}, Bb[4] = {0.f,0.f,0.f,0.f}, Cb[4] = {0.f,0.f,0.f,0.f};

#pragma unroll
    for (int k = 0; k < 8; k++) {
        const float4 xa = __ldcs(xp + (long long)k * (NN / 4));
        const float4 ya = __ldcs(yp + (long long)k * (NN / 4));
        const float4 xb = __ldcs(xp + (long long)(k + 8) * (NN / 4));
        const float4 yb = __ldcs(yp + (long long)(k + 8) * (NN / 4));

        const float da[4] = {xa.x - ya.x, xa.y - ya.y, xa.z - ya.z, xa.w - ya.w};
        const float db[4] = {xb.x - yb.x, xb.y - yb.y, xb.z - yb.z, xb.w - yb.w};
#pragma unroll
        for (int i = 0; i < 4; i++) {
            LA[i] = fmaf(da[i], pA, LA[i]);
            const float gA = sA * LA[i];
            BA[i] = fmaf(sA, gA, BA[i]);
            CA[i] = fmaf(gA, gA, CA[i]);

            LB[i] = fmaf(db[i], pB, LB[i]);
            const float gB = sB * LB[i];
            Bb[i] = fmaf(sB, gB, Bb[i]);
            Cb[i] = fmaf(gB, gB, Cb[i]);
        }
        pA *= R_DECAY;  sA *= R_GROW;
        pB *= R_DECAY;  sB *= R_GROW;
    }

    float T[4], Bo[4], Co[4];
#pragma unroll
    for (int i = 0; i < 4; i++) {
        T[i]  = LA[i] + LB[i];
        Bo[i] = BA[i] + fmaf(LA[i], alphaB, Bb[i]);
        Co[i] = CA[i] + fmaf(LA[i] * LA[i], alphaB, fmaf(2.0f * LA[i], Bb[i], Cb[i]));
    }

    const int idx = (b * CC + c) * NN + 4 * v;
    *(float4*)&g_Tc[idx] = make_float4(T[0],  T[1],  T[2],  T[3]);
    *(float4*)&g_Bc[idx] = make_float4(Bo[0], Bo[1], Bo[2], Bo[3]);
    *(float4*)&g_Cc[idx] = make_float4(Co[0], Co[1], Co[2], Co[3]);
}

// ---------------------------------------------------------------------------
// Pass 2 (fused final): grid (BB, QQ) x 256 threads.
// Thread (nl, sub): channel n = q*64+nl, chunks [sub*16, sub*16+16).
// Per-sub accumulators relative to unknown S_start:
//   al = sum A_c, be = sum (A_c*P_c + B_c), ga = sum (P_c^2 A_c + 2 P_c B_c + C_c)
// with P_c = local T-prefix; A_c = s0(c)^2 * GEO16 (analytic geometric).
// Sub results combined in smem in t-order; block-reduced; last block does the
// deterministic fixed-order final sum and mean (arrival counter, self-reset).
// ---------------------------------------------------------------------------
__global__ void __launch_bounds__(256) vr_pass2(float* __restrict__ out) {
    const int b   = blockIdx.x;
    const int q   = blockIdx.y;
    const int tid = threadIdx.x;
    const int nl  = tid & 63;
    const int sub = tid >> 6;
    const int n   = q * 64 + nl;
    const int c0  = sub * CPS;

    float s0 = __expf(((float)(c0 * TC) - 1023.0f) * 0.05f) * 0.05f;
    float P = 0.f, al = 0.f, be = 0.f, ga = 0.f;
#pragma unroll
    for (int j = 0; j < CPS; j++) {
        const int idx = (b * CC + c0 + j) * NN + n;
        const float T  = g_Tc[idx];
        const float Bv = g_Bc[idx];
        const float Cv = g_Cc[idx];
        const float A  = (s0 * s0) * GEO16;
        al += A;
        be += fmaf(A, P, Bv);
        ga += fmaf(P, fmaf(A, P, 2.0f * Bv), Cv);
        P  += T;
        s0 *= R_CHUNK;
    }

    __shared__ float sT[SUBS][64], sa[SUBS][64], sb[SUBS][64], sg[SUBS][64];
    __shared__ float sred[64];
    sT[sub][nl] = P;  sa[sub][nl] = al;  sb[sub][nl] = be;  sg[sub][nl] = ga;
    __syncthreads();

    if (sub == 0) {
        float S = 0.f, acc = 0.f;
#pragma unroll
        for (int ss = 0; ss < SUBS; ss++) {
            acc += fmaf(S * S, sa[ss][nl], fmaf(2.0f * S, sb[ss][nl], sg[ss][nl]));
            S += sT[ss][nl];
        }
        sred[nl] = acc;
    }
    __syncthreads();

    if (tid < 32) {
        float r = sred[tid] + sred[tid + 32];
        r += __shfl_down_sync(0xffffffffu, r, 16);
        r += __shfl_down_sync(0xffffffffu, r, 8);
        r += __shfl_down_sync(0xffffffffu, r, 4);
        r += __shfl_down_sync(0xffffffffu, r, 2);
        r += __shfl_down_sync(0xffffffffu, r, 1);
        if (tid == 0) {
            g_partial[b * QQ + q] = r;
            __threadfence();
            const unsigned t = atomicAdd(&g_done, 1u);
            if (t == (unsigned)(BB * QQ - 1)) {
                // Last block: deterministic fixed-order sum (value independent
                // of which block arrives last) + mean. L2 loads see fenced writes.
                float total = 0.f;
#pragma unroll
                for (int i = 0; i < BB * QQ; i++) total += __ldcg(&g_partial[i]);
                out[0] = total * (1.0f / (float)BB);
                g_done = 0;   // reset for next graph replay
            }
        }
    }
}

extern "C" void kernel_launch(void* const* d_in, const int* in_sizes, int n_in,
                              void* d_out, int out_size) {
    const float* x = (const float*)d_in[0];  // spike_output  [B,T,N]
    const float* y = (const float*)d_in[1];  // target_spikes [B,T,N]
    float* out = (float*)d_out;

    vr_pass1<<<dim3(BB, CC), NV>>>(x, y);
    vr_pass2<<<dim3(BB, QQ), 256>>>(out);
}